// round 2
// baseline (speedup 1.0000x reference)
#include <cuda_runtime.h>
#include <cuda_bf16.h>

// ---------------- problem constants ----------------
#define BB 4
#define NN 4096
#define JJ 512
#define DIMX 1024
#define CTXD 768
#define HEADS 16
#define DHEAD 64
#define HID (HEADS * DHEAD)   // 1024
#define MQ (BB * NN)          // 16384
#define MKV (BB * JJ)         // 2048
// sqrt(DIM_HEAD^-0.5) applied to both q and k
#define SQRT_SCALE 0.3535533905932738f

// ---------------- scratch (device globals; no allocation allowed) ----------
__device__ float g_xn[(size_t)MQ * DIMX];
__device__ float g_q[(size_t)MQ * HID];
__device__ float g_kv[(size_t)MKV * 2 * HID];
__device__ float g_att[(size_t)MQ * HID];
__device__ float g_proj[(size_t)MQ * DIMX];
__device__ int g_mask_mode;              // 0 = int32, 1 = float32, 2 = uint8
__device__ float g_maskf[BB * JJ];       // 1.0 = attend, 0.0 = masked out (j=0 always 1)

// ---------------- mask dtype sniffer + decode ----------------
__global__ void detect_mask_kernel(const void* mask) {
    if (threadIdx.x != 0) return;
    const unsigned char* p = (const unsigned char*)mask;
    const int nbytes = BB * (JJ - 1);  // 2044 = minimum valid byte length (uint8 case)
    bool i32ok = true;
    for (int i = 0; i < nbytes; i++) {
        if ((i & 3) != 0 && p[i] != 0) { i32ok = false; break; }
    }
    int mode;
    if (i32ok) {
        mode = 0;
    } else {
        const float* f = (const float*)mask;
        bool f32ok = true;
        for (int i = 0; i < nbytes / 4; i++) {
            float v = f[i];
            if (v != 0.0f && v != 1.0f) { f32ok = false; break; }
        }
        mode = f32ok ? 1 : 2;
    }
    g_mask_mode = mode;
}

__global__ void decode_mask_kernel(const void* mask) {
    int idx = blockIdx.x * blockDim.x + threadIdx.x;
    if (idx >= BB * JJ) return;
    int b = idx / JJ, j = idx % JJ;
    float on;
    if (j == 0) {
        on = 1.0f;  // padded always-true column
    } else {
        int mi = b * (JJ - 1) + (j - 1);
        int mode = g_mask_mode;
        bool v;
        if (mode == 0)      v = ((const int*)mask)[mi] != 0;
        else if (mode == 1) v = ((const float*)mask)[mi] != 0.0f;
        else                v = ((const unsigned char*)mask)[mi] != 0;
        on = v ? 1.0f : 0.0f;
    }
    g_maskf[idx] = on;
}

// ---------------- LayerNorm (gamma only) ----------------
__global__ void __launch_bounds__(256) ln_kernel(const float* __restrict__ X,
                                                 const float* __restrict__ gamma,
                                                 float* __restrict__ Y, int C) {
    int row = blockIdx.x;
    const float* x = X + (size_t)row * C;
    float* y = Y + (size_t)row * C;
    float s = 0.f, ss = 0.f;
    for (int i = threadIdx.x; i < C; i += blockDim.x) {
        float v = x[i];
        s += v;
        ss += v * v;
    }
    __shared__ float red[64];
#pragma unroll
    for (int o = 16; o > 0; o >>= 1) {
        s += __shfl_down_sync(0xffffffffu, s, o);
        ss += __shfl_down_sync(0xffffffffu, ss, o);
    }
    int w = threadIdx.x >> 5, l = threadIdx.x & 31;
    if (l == 0) { red[w] = s; red[32 + w] = ss; }
    __syncthreads();
    if (threadIdx.x == 0) {
        float S = 0.f, SS = 0.f;
        int nw = blockDim.x >> 5;
        for (int i = 0; i < nw; i++) { S += red[i]; SS += red[32 + i]; }
        float mu = S / C;
        float var = SS / C - mu * mu;
        red[0] = mu;
        red[1] = rsqrtf(var + 1e-5f);
    }
    __syncthreads();
    float mu = red[0], rs = red[1];
    for (int i = threadIdx.x; i < C; i += blockDim.x)
        y[i] = (x[i] - mu) * rs * gamma[i];
}

// ---------------- SGEMM: C[M,N] = A[M,K] * B[K,N], row-major ----------------
// 128x128 tile, BK=16, 256 threads, 8x8 per-thread micro-tile.
// Columns col < scaleLimit get multiplied by `scale` in the epilogue.
__global__ void __launch_bounds__(256) sgemm128(const float* __restrict__ A,
                                                const float* __restrict__ B,
                                                float* __restrict__ C,
                                                int M, int N, int K,
                                                float scale, int scaleLimit) {
    __shared__ float As[16][132];  // transposed A tile
    __shared__ float Bs[16][132];
    int tid = threadIdx.x;
    int rowBase = blockIdx.y * 128;
    int colBase = blockIdx.x * 128;
    int ty = tid >> 4, tx = tid & 15;
    float acc[8][8];
#pragma unroll
    for (int i = 0; i < 8; i++)
#pragma unroll
        for (int j = 0; j < 8; j++) acc[i][j] = 0.f;

    for (int k0 = 0; k0 < K; k0 += 16) {
#pragma unroll
        for (int it = 0; it < 2; it++) {
            int idx = tid + it * 256;           // 0..511
            int r = idx >> 2;                   // 0..127
            int c4 = (idx & 3) * 4;             // 0,4,8,12
            float4 v = *(const float4*)(A + (size_t)(rowBase + r) * K + k0 + c4);
            As[c4 + 0][r] = v.x;
            As[c4 + 1][r] = v.y;
            As[c4 + 2][r] = v.z;
            As[c4 + 3][r] = v.w;
        }
#pragma unroll
        for (int it = 0; it < 2; it++) {
            int idx = tid + it * 256;           // 0..511
            int r = idx >> 5;                   // 0..15
            int c4 = (idx & 31) * 4;            // 0..124
            float4 v = *(const float4*)(B + (size_t)(k0 + r) * N + colBase + c4);
            *(float4*)&Bs[r][c4] = v;
        }
        __syncthreads();
#pragma unroll
        for (int kk = 0; kk < 16; kk++) {
            float a[8], b[8];
#pragma unroll
            for (int i = 0; i < 8; i++) a[i] = As[kk][ty * 8 + i];
#pragma unroll
            for (int j = 0; j < 8; j++) b[j] = Bs[kk][tx * 8 + j];
#pragma unroll
            for (int i = 0; i < 8; i++)
#pragma unroll
                for (int j = 0; j < 8; j++) acc[i][j] += a[i] * b[j];
        }
        __syncthreads();
    }
#pragma unroll
    for (int i = 0; i < 8; i++) {
        int r = rowBase + ty * 8 + i;
#pragma unroll
        for (int j = 0; j < 8; j++) {
            int c = colBase + tx * 8 + j;
            float v = acc[i][j];
            if (c < scaleLimit) v *= scale;
            C[(size_t)r * N + c] = v;
        }
    }
}

// ---------------- fused attention (flash-style, fp32) ----------------
// grid: (B*HEADS, N/64), block: 256 threads.
// Each block: 64 queries x full J=512 keys in chunks of 32, online softmax.
__global__ void __launch_bounds__(256) attn_kernel(const float* __restrict__ Q,
                                                   const float* __restrict__ KV,
                                                   float* __restrict__ Og) {
    int bh = blockIdx.x;
    int b = bh >> 4;
    int h = bh & 15;
    int n0 = blockIdx.y * 64;
    const float* qp = Q + ((size_t)(b * NN + n0)) * HID + h * DHEAD;
    const float* kp = KV + (size_t)b * JJ * (2 * HID) + h * DHEAD;
    const float* vp = kp + HID;

    __shared__ float Qs[64][65];
    __shared__ float KVs[32][65];
    __shared__ float Ssh[64][33];
    __shared__ float mrow[64], lrow[64], arow[64];
    __shared__ float mflag[32];  // 1.0f means MASKED OUT

    int tid = threadIdx.x;
    int ty = tid >> 4, tx = tid & 15;

    for (int i = tid; i < 64 * 64; i += 256) {
        int r = i >> 6, c = i & 63;
        Qs[r][c] = qp[(size_t)r * HID + c];
    }
    if (tid < 64) { mrow[tid] = -3.0e38f; lrow[tid] = 0.f; }
    float o[4][4];
#pragma unroll
    for (int i = 0; i < 4; i++)
#pragma unroll
        for (int j = 0; j < 4; j++) o[i][j] = 0.f;
    __syncthreads();

    for (int c0 = 0; c0 < JJ; c0 += 32) {
        // load K chunk
        for (int i = tid; i < 32 * 64; i += 256) {
            int r = i >> 6, cc = i & 63;
            KVs[r][cc] = kp[(size_t)(c0 + r) * (2 * HID) + cc];
        }
        if (tid < 32) {
            mflag[tid] = (g_maskf[b * JJ + c0 + tid] == 0.f) ? 1.f : 0.f;
        }
        __syncthreads();

        // S = Q K^T : per-thread 4 q-rows x 2 key-cols
        float sacc[4][2];
#pragma unroll
        for (int i = 0; i < 4; i++) { sacc[i][0] = 0.f; sacc[i][1] = 0.f; }
#pragma unroll 8
        for (int d = 0; d < 64; d++) {
            float k0v = KVs[tx * 2 + 0][d];
            float k1v = KVs[tx * 2 + 1][d];
#pragma unroll
            for (int i = 0; i < 4; i++) {
                float qv = Qs[ty * 4 + i][d];
                sacc[i][0] += qv * k0v;
                sacc[i][1] += qv * k1v;
            }
        }
#pragma unroll
        for (int i = 0; i < 4; i++)
#pragma unroll
            for (int j = 0; j < 2; j++) {
                float v = sacc[i][j];
                if (mflag[tx * 2 + j] != 0.f) v = -1e30f;
                Ssh[ty * 4 + i][tx * 2 + j] = v;
            }
        __syncthreads();  // S reads of K complete; Ssh written

        // load V chunk (all threads) while threads<64 also do softmax
        for (int i = tid; i < 32 * 64; i += 256) {
            int r = i >> 6, cc = i & 63;
            KVs[r][cc] = vp[(size_t)(c0 + r) * (2 * HID) + cc];
        }
        if (tid < 64) {
            float m = mrow[tid];
            float mloc = -3.0e38f;
#pragma unroll
            for (int j = 0; j < 32; j++) mloc = fmaxf(mloc, Ssh[tid][j]);
            float mnew = fmaxf(m, mloc);
            float alpha = __expf(m - mnew);
            float sum = 0.f;
#pragma unroll
            for (int j = 0; j < 32; j++) {
                float p = __expf(Ssh[tid][j] - mnew);
                Ssh[tid][j] = p;
                sum += p;
            }
            lrow[tid] = lrow[tid] * alpha + sum;
            mrow[tid] = mnew;
            arow[tid] = alpha;
        }
        __syncthreads();

        // rescale accumulators, then O += P * V
#pragma unroll
        for (int i = 0; i < 4; i++) {
            float a = arow[ty * 4 + i];
#pragma unroll
            for (int j = 0; j < 4; j++) o[i][j] *= a;
        }
#pragma unroll 4
        for (int kk = 0; kk < 32; kk++) {
            float pv[4], vv[4];
#pragma unroll
            for (int i = 0; i < 4; i++) pv[i] = Ssh[ty * 4 + i][kk];
#pragma unroll
            for (int j = 0; j < 4; j++) vv[j] = KVs[kk][tx * 4 + j];
#pragma unroll
            for (int i = 0; i < 4; i++)
#pragma unroll
                for (int j = 0; j < 4; j++) o[i][j] += pv[i] * vv[j];
        }
        __syncthreads();  // done with Ssh / KVs for this chunk
    }

#pragma unroll
    for (int i = 0; i < 4; i++) {
        int r = ty * 4 + i;
        float inv = 1.f / lrow[r];
#pragma unroll
        for (int j = 0; j < 4; j++) {
            Og[((size_t)(b * NN + n0 + r)) * HID + h * DHEAD + tx * 4 + j] = o[i][j] * inv;
        }
    }
}

// ---------------- launch ----------------
extern "C" void kernel_launch(void* const* d_in, const int* in_sizes, int n_in,
                              void* d_out, int out_size) {
    const float* x = (const float*)d_in[0];
    const float* ctx = (const float*)d_in[1];
    const void* mask = d_in[2];
    const float* gamma_x = (const float*)d_in[3];
    const float* Wq = (const float*)d_in[4];
    const float* Wkv = (const float*)d_in[5];
    const float* Wo = (const float*)d_in[6];
    const float* gamma_out = (const float*)d_in[7];
    float* out = (float*)d_out;

    float *xn, *q, *kv, *att, *proj;
    cudaGetSymbolAddress((void**)&xn, g_xn);
    cudaGetSymbolAddress((void**)&q, g_q);
    cudaGetSymbolAddress((void**)&kv, g_kv);
    cudaGetSymbolAddress((void**)&att, g_att);
    cudaGetSymbolAddress((void**)&proj, g_proj);

    // 0. decode mask (dtype-sniffing, deterministic)
    detect_mask_kernel<<<1, 32>>>(mask);
    decode_mask_kernel<<<(BB * JJ + 255) / 256, 256>>>(mask);

    // 1. xn = LN(x) * gamma_x
    ln_kernel<<<MQ, 256>>>(x, gamma_x, xn, DIMX);

    // 2. q = (xn @ Wq) * sqrt(scale)
    {
        dim3 grid(HID / 128, MQ / 128);
        sgemm128<<<grid, 256>>>(xn, Wq, q, MQ, HID, DIMX, SQRT_SCALE, HID);
    }

    // 3. kv = ctx @ Wkv ; k-half scaled by sqrt(scale)
    {
        dim3 grid((2 * HID) / 128, MKV / 128);
        sgemm128<<<grid, 256>>>(ctx, Wkv, kv, MKV, 2 * HID, CTXD, SQRT_SCALE, HID);
    }

    // 4. attention
    {
        dim3 grid(BB * HEADS, NN / 64);
        attn_kernel<<<grid, 256>>>(q, kv, att);
    }

    // 5. proj = att @ Wo
    {
        dim3 grid(DIMX / 128, MQ / 128);
        sgemm128<<<grid, 256>>>(att, Wo, proj, MQ, DIMX, HID, 1.0f, 0);
    }

    // 6. out = LN(proj) * gamma_out
    ln_kernel<<<MQ, 256>>>(proj, gamma_out, out, DIMX);
}

// round 3
// speedup vs baseline: 2.8282x; 2.8282x over previous
#include <cuda_runtime.h>
#include <cuda_bf16.h>

// ---------------- problem constants ----------------
#define BB 4
#define NN 4096
#define JJ 512
#define DIMX 1024
#define CTXD 768
#define HEADS 16
#define DHEAD 64
#define HID (HEADS * DHEAD)   // 1024
#define MQ (BB * NN)          // 16384
#define MKV (BB * JJ)         // 2048
#define SQRT_SCALE 0.3535533905932738f

// ---------------- scratch ----------------
__device__ float g_xn[(size_t)MQ * DIMX];
__device__ float g_q[(size_t)MQ * HID];
__device__ float g_kv[(size_t)MKV * 2 * HID];
__device__ float g_att[(size_t)MQ * HID];
__device__ float g_proj[(size_t)MQ * DIMX];
__device__ int g_mask_mode;
__device__ float g_maskf[BB * JJ];  // 1.0 = attend, 0.0 = masked

// ---------------- small helpers ----------------
__device__ __forceinline__ unsigned f2tf(float f) {
    unsigned r;
    asm("cvt.rna.tf32.f32 %0, %1;" : "=r"(r) : "f"(f));
    return r;
}
__device__ __forceinline__ void mma_tf32(float c[4], const unsigned a[4], const unsigned b[2]) {
    asm volatile(
        "mma.sync.aligned.m16n8k8.row.col.f32.tf32.tf32.f32 "
        "{%0,%1,%2,%3}, {%4,%5,%6,%7}, {%8,%9}, {%0,%1,%2,%3};"
        : "+f"(c[0]), "+f"(c[1]), "+f"(c[2]), "+f"(c[3])
        : "r"(a[0]), "r"(a[1]), "r"(a[2]), "r"(a[3]), "r"(b[0]), "r"(b[1]));
}
__device__ __forceinline__ void cp16(void* dst, const void* src) {
    unsigned d = (unsigned)__cvta_generic_to_shared(dst);
    asm volatile("cp.async.cg.shared.global [%0], [%1], 16;" ::"r"(d), "l"(src));
}
#define CP_COMMIT() asm volatile("cp.async.commit_group;")
#define CP_WAIT(n) asm volatile("cp.async.wait_group %0;" ::"n"(n))

// ---------------- mask dtype sniffer + decode ----------------
__global__ void detect_mask_kernel(const void* mask) {
    if (threadIdx.x != 0) return;
    const unsigned char* p = (const unsigned char*)mask;
    const int nbytes = BB * (JJ - 1);
    bool i32ok = true;
    for (int i = 0; i < nbytes; i++)
        if ((i & 3) != 0 && p[i] != 0) { i32ok = false; break; }
    int mode;
    if (i32ok) mode = 0;
    else {
        const float* f = (const float*)mask;
        bool f32ok = true;
        for (int i = 0; i < nbytes / 4; i++) {
            float v = f[i];
            if (v != 0.0f && v != 1.0f) { f32ok = false; break; }
        }
        mode = f32ok ? 1 : 2;
    }
    g_mask_mode = mode;
}

__global__ void decode_mask_kernel(const void* mask) {
    int idx = blockIdx.x * blockDim.x + threadIdx.x;
    if (idx >= BB * JJ) return;
    int b = idx / JJ, j = idx % JJ;
    float on;
    if (j == 0) on = 1.0f;
    else {
        int mi = b * (JJ - 1) + (j - 1);
        int mode = g_mask_mode;
        bool v;
        if (mode == 0)      v = ((const int*)mask)[mi] != 0;
        else if (mode == 1) v = ((const float*)mask)[mi] != 0.0f;
        else                v = ((const unsigned char*)mask)[mi] != 0;
        on = v ? 1.0f : 0.0f;
    }
    g_maskf[idx] = on;
}

// ---------------- LayerNorm (gamma only) ----------------
__global__ void __launch_bounds__(256) ln_kernel(const float* __restrict__ X,
                                                 const float* __restrict__ gamma,
                                                 float* __restrict__ Y, int C) {
    int row = blockIdx.x;
    const float* x = X + (size_t)row * C;
    float* y = Y + (size_t)row * C;
    float s = 0.f, ss = 0.f;
    for (int i = threadIdx.x; i < C; i += blockDim.x) {
        float v = x[i];
        s += v;
        ss += v * v;
    }
    __shared__ float red[64];
#pragma unroll
    for (int o = 16; o > 0; o >>= 1) {
        s += __shfl_down_sync(0xffffffffu, s, o);
        ss += __shfl_down_sync(0xffffffffu, ss, o);
    }
    int w = threadIdx.x >> 5, l = threadIdx.x & 31;
    if (l == 0) { red[w] = s; red[32 + w] = ss; }
    __syncthreads();
    if (threadIdx.x == 0) {
        float S = 0.f, SS = 0.f;
        int nw = blockDim.x >> 5;
        for (int i = 0; i < nw; i++) { S += red[i]; SS += red[32 + i]; }
        float mu = S / C;
        float var = SS / C - mu * mu;
        red[0] = mu;
        red[1] = rsqrtf(var + 1e-5f);
    }
    __syncthreads();
    float mu = red[0], rs = red[1];
    for (int i = threadIdx.x; i < C; i += blockDim.x)
        y[i] = (x[i] - mu) * rs * gamma[i];
}

// ---------------- TF32 GEMM: C[M,N] = A[M,K]*B[K,N] ----------------
// 128x128x16 tile, 128 threads (4 warps, 2x2), warp tile 64x64.
// cp.async double-buffered. Cols < scaleLimit multiplied by scale.
__global__ void __launch_bounds__(128) sgemm_tf32(const float* __restrict__ A,
                                                  const float* __restrict__ B,
                                                  float* __restrict__ C,
                                                  int M, int N, int K,
                                                  float scale, int scaleLimit) {
    __shared__ __align__(16) float As[2][128][20];
    __shared__ __align__(16) float Bs[2][16][132];
    const int tid = threadIdx.x;
    const int lane = tid & 31, wid = tid >> 5;
    const int warpRow = (wid & 1) * 64, warpCol = (wid >> 1) * 64;
    const int gr = lane >> 2, gc = lane & 3;
    const int rowBase = blockIdx.y * 128;
    const int colBase = blockIdx.x * 128;

    float acc[4][8][4];
#pragma unroll
    for (int mf = 0; mf < 4; mf++)
#pragma unroll
        for (int nf = 0; nf < 8; nf++)
#pragma unroll
            for (int i = 0; i < 4; i++) acc[mf][nf][i] = 0.f;

    auto prefetch = [&](int s, int k0) {
#pragma unroll
        for (int p = 0; p < 4; p++) {
            int idx = tid + p * 128;
            int r = idx >> 2, c4 = (idx & 3) * 4;
            cp16(&As[s][r][c4], A + (size_t)(rowBase + r) * K + k0 + c4);
        }
#pragma unroll
        for (int p = 0; p < 4; p++) {
            int idx = tid + p * 128;
            int r = idx >> 5, c4 = (idx & 31) * 4;
            cp16(&Bs[s][r][c4], B + (size_t)(k0 + r) * N + colBase + c4);
        }
    };

    const int nk = K / 16;
    prefetch(0, 0);
    CP_COMMIT();

    for (int kt = 0; kt < nk; kt++) {
        int s = kt & 1;
        if (kt + 1 < nk) prefetch(s ^ 1, (kt + 1) * 16);
        CP_COMMIT();
        CP_WAIT(1);
        __syncthreads();
#pragma unroll
        for (int ks = 0; ks < 2; ks++) {
            int k = ks * 8;
            unsigned a[4][4], b[8][2];
#pragma unroll
            for (int mf = 0; mf < 4; mf++) {
                int mb = warpRow + mf * 16;
                a[mf][0] = f2tf(As[s][mb + gr][k + gc]);
                a[mf][1] = f2tf(As[s][mb + gr + 8][k + gc]);
                a[mf][2] = f2tf(As[s][mb + gr][k + gc + 4]);
                a[mf][3] = f2tf(As[s][mb + gr + 8][k + gc + 4]);
            }
#pragma unroll
            for (int nf = 0; nf < 8; nf++) {
                int nb = warpCol + nf * 8;
                b[nf][0] = f2tf(Bs[s][k + gc][nb + gr]);
                b[nf][1] = f2tf(Bs[s][k + gc + 4][nb + gr]);
            }
#pragma unroll
            for (int mf = 0; mf < 4; mf++)
#pragma unroll
                for (int nf = 0; nf < 8; nf++) mma_tf32(acc[mf][nf], a[mf], b[nf]);
        }
        __syncthreads();
    }

#pragma unroll
    for (int mf = 0; mf < 4; mf++) {
        int row = rowBase + warpRow + mf * 16 + gr;
#pragma unroll
        for (int nf = 0; nf < 8; nf++) {
            int col = colBase + warpCol + nf * 8 + 2 * gc;
            float sc = (col < scaleLimit) ? scale : 1.f;
            float2 v0 = make_float2(acc[mf][nf][0] * sc, acc[mf][nf][1] * sc);
            float2 v1 = make_float2(acc[mf][nf][2] * sc, acc[mf][nf][3] * sc);
            *(float2*)(C + (size_t)row * N + col) = v0;
            *(float2*)(C + (size_t)(row + 8) * N + col) = v1;
        }
    }
}

// ---------------- flash attention, tf32 tensor cores ----------------
// grid (B*H, N/128), 256 threads (8 warps). Each warp owns a 16-query strip.
// KV processed in chunks of 64 with cp.async pipelining.
__global__ void __launch_bounds__(256) attn_tc(const float* __restrict__ Q,
                                               const float* __restrict__ KV,
                                               float* __restrict__ Og) {
    extern __shared__ float sm[];
    float(*Qs)[68] = (float(*)[68])sm;                          // 128x68
    float(*Ks)[68] = (float(*)[68])(sm + 128 * 68);             // 64x68
    float(*Vs)[68] = (float(*)[68])(sm + 128 * 68 + 64 * 68);   // 64x68
    float(*Ps)[68] = (float(*)[68])(sm + 128 * 68 + 2 * 64 * 68);  // 128x68

    const int bh = blockIdx.x;
    const int b = bh >> 4, h = bh & 15;
    const int n0 = blockIdx.y * 128;
    const float* qp = Q + ((size_t)(b * NN + n0)) * HID + h * DHEAD;
    const float* kp = KV + (size_t)b * JJ * (2 * HID) + h * DHEAD;
    const float* vp = kp + HID;

    const int tid = threadIdx.x;
    const int lane = tid & 31, wid = tid >> 5;
    const int warpQ = wid * 16;
    const int gr = lane >> 2, gc = lane & 3;

    // prefetch Q (8 passes) + K chunk 0 (4 passes) as group 0
    {
#pragma unroll
        for (int p = 0; p < 8; p++) {
            int idx = tid + p * 256;
            int r = idx >> 4, c4 = (idx & 15) * 4;
            cp16(&Qs[r][c4], qp + (size_t)r * HID + c4);
        }
#pragma unroll
        for (int p = 0; p < 4; p++) {
            int idx = tid + p * 256;
            int r = idx >> 4, c4 = (idx & 15) * 4;
            cp16(&Ks[r][c4], kp + (size_t)r * (2 * HID) + c4);
        }
        CP_COMMIT();
    }

    float o[8][4];
#pragma unroll
    for (int nf = 0; nf < 8; nf++)
#pragma unroll
        for (int i = 0; i < 4; i++) o[nf][i] = 0.f;
    float m0 = -1e30f, m1 = -1e30f, l0 = 0.f, l1 = 0.f;

    for (int c = 0; c < 8; c++) {
        int c0 = c * 64;
        // prefetch V(c)
#pragma unroll
        for (int p = 0; p < 4; p++) {
            int idx = tid + p * 256;
            int r = idx >> 4, c4 = (idx & 15) * 4;
            cp16(&Vs[r][c4], vp + (size_t)(c0 + r) * (2 * HID) + c4);
        }
        CP_COMMIT();
        CP_WAIT(1);  // K(c) (and Q) ready
        __syncthreads();

        // ---- S = Q K^T over this chunk ----
        float s[8][4];
#pragma unroll
        for (int nf = 0; nf < 8; nf++)
#pragma unroll
            for (int i = 0; i < 4; i++) s[nf][i] = 0.f;
#pragma unroll
        for (int kk = 0; kk < 8; kk++) {
            unsigned aq[4];
            aq[0] = f2tf(Qs[warpQ + gr][kk * 8 + gc]);
            aq[1] = f2tf(Qs[warpQ + gr + 8][kk * 8 + gc]);
            aq[2] = f2tf(Qs[warpQ + gr][kk * 8 + gc + 4]);
            aq[3] = f2tf(Qs[warpQ + gr + 8][kk * 8 + gc + 4]);
#pragma unroll
            for (int nf = 0; nf < 8; nf++) {
                unsigned bk[2];
                bk[0] = f2tf(Ks[nf * 8 + gr][kk * 8 + gc]);
                bk[1] = f2tf(Ks[nf * 8 + gr][kk * 8 + gc + 4]);
                mma_tf32(s[nf], aq, bk);
            }
        }

        // ---- mask ----
#pragma unroll
        for (int nf = 0; nf < 8; nf++) {
            int col = c0 + nf * 8 + 2 * gc;
            float mk0 = g_maskf[b * JJ + col];
            float mk1 = g_maskf[b * JJ + col + 1];
            if (mk0 == 0.f) { s[nf][0] = -1e30f; s[nf][2] = -1e30f; }
            if (mk1 == 0.f) { s[nf][1] = -1e30f; s[nf][3] = -1e30f; }
        }

        // ---- online softmax (rows warpQ+gr, warpQ+gr+8) ----
        float rm0 = -1e30f, rm1 = -1e30f;
#pragma unroll
        for (int nf = 0; nf < 8; nf++) {
            rm0 = fmaxf(rm0, fmaxf(s[nf][0], s[nf][1]));
            rm1 = fmaxf(rm1, fmaxf(s[nf][2], s[nf][3]));
        }
        rm0 = fmaxf(rm0, __shfl_xor_sync(0xffffffffu, rm0, 1));
        rm0 = fmaxf(rm0, __shfl_xor_sync(0xffffffffu, rm0, 2));
        rm1 = fmaxf(rm1, __shfl_xor_sync(0xffffffffu, rm1, 1));
        rm1 = fmaxf(rm1, __shfl_xor_sync(0xffffffffu, rm1, 2));
        float mn0 = fmaxf(m0, rm0), mn1 = fmaxf(m1, rm1);
        float al0 = __expf(m0 - mn0), al1 = __expf(m1 - mn1);
        float sum0 = 0.f, sum1 = 0.f;
#pragma unroll
        for (int nf = 0; nf < 8; nf++) {
            s[nf][0] = __expf(s[nf][0] - mn0);
            s[nf][1] = __expf(s[nf][1] - mn0);
            s[nf][2] = __expf(s[nf][2] - mn1);
            s[nf][3] = __expf(s[nf][3] - mn1);
            sum0 += s[nf][0] + s[nf][1];
            sum1 += s[nf][2] + s[nf][3];
        }
        sum0 += __shfl_xor_sync(0xffffffffu, sum0, 1);
        sum0 += __shfl_xor_sync(0xffffffffu, sum0, 2);
        sum1 += __shfl_xor_sync(0xffffffffu, sum1, 1);
        sum1 += __shfl_xor_sync(0xffffffffu, sum1, 2);
        l0 = l0 * al0 + sum0;
        l1 = l1 * al1 + sum1;
        m0 = mn0;
        m1 = mn1;

        // write P strip to smem (layout shuffle C-frag -> A-frag)
#pragma unroll
        for (int nf = 0; nf < 8; nf++) {
            int col = nf * 8 + 2 * gc;
            *(float2*)&Ps[warpQ + gr][col] = make_float2(s[nf][0], s[nf][1]);
            *(float2*)&Ps[warpQ + gr + 8][col] = make_float2(s[nf][2], s[nf][3]);
        }
        __syncthreads();  // Ks free, Ps visible (own warp only, but需要 barrier for Ks prefetch)

        if (c < 7) {
            int cn = (c + 1) * 64;
#pragma unroll
            for (int p = 0; p < 4; p++) {
                int idx = tid + p * 256;
                int r = idx >> 4, c4 = (idx & 15) * 4;
                cp16(&Ks[r][c4], kp + (size_t)(cn + r) * (2 * HID) + c4);
            }
            CP_COMMIT();
            CP_WAIT(1);  // V(c) ready
        } else {
            CP_COMMIT();
            CP_WAIT(0);
        }
        __syncthreads();

        // ---- O = O*alpha + P V ----
#pragma unroll
        for (int nf = 0; nf < 8; nf++) {
            o[nf][0] *= al0;
            o[nf][1] *= al0;
            o[nf][2] *= al1;
            o[nf][3] *= al1;
        }
#pragma unroll
        for (int kk = 0; kk < 8; kk++) {
            unsigned ap[4];
            ap[0] = f2tf(Ps[warpQ + gr][kk * 8 + gc]);
            ap[1] = f2tf(Ps[warpQ + gr + 8][kk * 8 + gc]);
            ap[2] = f2tf(Ps[warpQ + gr][kk * 8 + gc + 4]);
            ap[3] = f2tf(Ps[warpQ + gr + 8][kk * 8 + gc + 4]);
#pragma unroll
            for (int nf = 0; nf < 8; nf++) {
                unsigned bv[2];
                bv[0] = f2tf(Vs[kk * 8 + gc][nf * 8 + gr]);
                bv[1] = f2tf(Vs[kk * 8 + gc + 4][nf * 8 + gr]);
                mma_tf32(o[nf], ap, bv);
            }
        }
        __syncthreads();  // Vs / Ps free
    }

    float inv0 = 1.f / l0, inv1 = 1.f / l1;
#pragma unroll
    for (int nf = 0; nf < 8; nf++) {
        int colg = h * DHEAD + nf * 8 + 2 * gc;
        size_t r0 = (size_t)(b * NN + n0 + warpQ + gr);
        size_t r1 = r0 + 8;
        *(float2*)(Og + r0 * HID + colg) = make_float2(o[nf][0] * inv0, o[nf][1] * inv0);
        *(float2*)(Og + r1 * HID + colg) = make_float2(o[nf][2] * inv1, o[nf][3] * inv1);
    }
}

// ---------------- launch ----------------
extern "C" void kernel_launch(void* const* d_in, const int* in_sizes, int n_in,
                              void* d_out, int out_size) {
    const float* x = (const float*)d_in[0];
    const float* ctx = (const float*)d_in[1];
    const void* mask = d_in[2];
    const float* gamma_x = (const float*)d_in[3];
    const float* Wq = (const float*)d_in[4];
    const float* Wkv = (const float*)d_in[5];
    const float* Wo = (const float*)d_in[6];
    const float* gamma_out = (const float*)d_in[7];
    float* out = (float*)d_out;

    float *xn, *q, *kv, *att, *proj;
    cudaGetSymbolAddress((void**)&xn, g_xn);
    cudaGetSymbolAddress((void**)&q, g_q);
    cudaGetSymbolAddress((void**)&kv, g_kv);
    cudaGetSymbolAddress((void**)&att, g_att);
    cudaGetSymbolAddress((void**)&proj, g_proj);

    detect_mask_kernel<<<1, 32>>>(mask);
    decode_mask_kernel<<<(BB * JJ + 255) / 256, 256>>>(mask);

    ln_kernel<<<MQ, 256>>>(x, gamma_x, xn, DIMX);

    {
        dim3 grid(HID / 128, MQ / 128);
        sgemm_tf32<<<grid, 128>>>(xn, Wq, q, MQ, HID, DIMX, SQRT_SCALE, HID);
    }
    {
        dim3 grid((2 * HID) / 128, MKV / 128);
        sgemm_tf32<<<grid, 128>>>(ctx, Wkv, kv, MKV, 2 * HID, CTXD, SQRT_SCALE, HID);
    }
    {
        const int smem = (128 * 68 + 2 * 64 * 68 + 128 * 68) * 4;  // 104448
        cudaFuncSetAttribute(attn_tc, cudaFuncAttributeMaxDynamicSharedMemorySize, smem);
        dim3 grid(BB * HEADS, NN / 128);
        attn_tc<<<grid, 256, smem>>>(q, kv, att);
    }
    {
        dim3 grid(DIMX / 128, MQ / 128);
        sgemm_tf32<<<grid, 128>>>(att, Wo, proj, MQ, DIMX, HID, 1.0f, 0);
    }
    ln_kernel<<<MQ, 256>>>(proj, gamma_out, out, DIMX);
}